// round 12
// baseline (speedup 1.0000x reference)
#include <cuda_runtime.h>
#include <cuda_bf16.h>
#include <math.h>
#include <stdint.h>

#define DIM   512
#define N_ELEM (DIM*DIM)       // 262144
#define KFLAT 1024             // DT*2
#define NB    32               // persistent CTAs, each owns 16 rows
#define NTH   512
#define ROWS_PER  16
#define ELEMS_PER 8192         // 16*512 per CTA
#define NPT_E 16               // 8192/512

// dynamic smem layout
#define BAS_HI 0               // basis hi: 16 k-chunks x 2KB (16 rows x 128B, SW128)
#define BAS_LO 32768           // basis lo: 32KB
#define BBUF0  65536           // B double buffer: 2 x 64KB (512 rows x 128B)
#define BCHUNK 65536
#define SMEM_DYN (65536 + 2*BCHUNK)   // 192KB

// ---------------- device state ----------------
__device__ float g_A[N_ELEM];          // y
__device__ float g_K[7][N_ELEM];       // k1..k7 (no split-K)
__device__ float g_ynew[N_ELEM];
__device__ __align__(16) __nv_bfloat16 g_Chi[DIM*KFLAT]; // C hi (row=out col, K contiguous)
__device__ __align__(16) __nv_bfloat16 g_Clo[DIM*KFLAT]; // C lo
__device__ float g_red[5*NB];          // slots: 0=d0,1=d1,2=d2, 3/4=step parity
__device__ int   g_bar_cnt;
__device__ int   g_bar_epoch;

// stage coefficient tables (Dormand-Prince)
__constant__ float STG_C[8][6] = {
  {0.f,0.f,0.f,0.f,0.f,0.f},
  {1.f,0.f,0.f,0.f,0.f,0.f},
  {0.2f,0.f,0.f,0.f,0.f,0.f},
  {3.f/40.f, 9.f/40.f, 0.f,0.f,0.f,0.f},
  {44.f/45.f, -56.f/15.f, 32.f/9.f, 0.f,0.f,0.f},
  {19372.f/6561.f, -25360.f/2187.f, 64448.f/6561.f, -212.f/729.f,0.f,0.f},
  {9017.f/3168.f, -355.f/33.f, 46732.f/5247.f, 49.f/176.f, -5103.f/18656.f, 0.f},
  {35.f/384.f, 0.f, 500.f/1113.f, 125.f/192.f, -2187.f/6784.f, 11.f/84.f},
};
__constant__ float STG_T[8] = {0.f, 1.f, 0.2f, 0.3f, 0.8f, 8.f/9.f, 1.f, 1.f};
__constant__ float ERR_C[6] = { 71.f/57600.f, -71.f/16695.f, 71.f/1920.f,
                                -17253.f/339200.f, 22.f/525.f, -1.f/40.f };
__constant__ int ERR_IDX[6] = {0, 2, 3, 4, 5, 6};

#define SWZ128(o) ((o) ^ (((o) >> 3) & 0x70))

__device__ __forceinline__ uint32_t smem_u32(const void* p) {
  uint32_t a;
  asm("{ .reg .u64 t; cvta.to.shared.u64 t, %1; cvt.u32.u64 %0, t; }" : "=r"(a) : "l"(p));
  return a;
}

#define CP_ASYNC16(sm, gp) \
  asm volatile("cp.async.cg.shared.global [%0], [%1], 16;" :: "r"(sm), "l"(gp) : "memory")
#define CP_COMMIT()  asm volatile("cp.async.commit_group;" ::: "memory")
#define CP_WAIT1()   asm volatile("cp.async.wait_group 1;" ::: "memory")
#define CP_WAIT0()   asm volatile("cp.async.wait_group 0;" ::: "memory")

// ---------------- grid barrier (32 CTAs) ----------------
__device__ __forceinline__ void gridbar(int* s_epoch) {
  __syncthreads();
  if (threadIdx.x == 0) {
    int e = ++(*s_epoch);
    __threadfence();
    if (atomicAdd(&g_bar_cnt, 1) == NB - 1) {
      g_bar_cnt = 0;
      __threadfence();
      atomicExch(&g_bar_epoch, e);
    } else {
      while (*((volatile int*)&g_bar_epoch) < e) { }
    }
    __threadfence();
  }
  __syncthreads();
}

// ---------------- elementwise stage: ytmp + bf16 hi/lo basis into SMEM ------
__device__ void stage_dev(int sid, int nK, int writeYnew,
                          float hs, float t, int id, char* dynsm) {
  float ts = t + STG_T[sid] * hs;
  #pragma unroll 4
  for (int it = 0; it < NPT_E; it++) {
    int e = threadIdx.x + it * NTH;          // 0..8191 local element
    int i = id * ELEMS_PER + e;              // global element (row-major)
    float y = g_A[i];
    float yt = y;
    if (nK > 0) {
      float acc = 0.f;
      for (int j = 0; j < nK; j++)
        acc += STG_C[sid][j] * g_K[j][i];
      yt = y + hs * acc;
    }
    if (writeYnew) g_ynew[i] = yt;
    float ph = yt + ts;                      // TA=1, TB=1, TC=0
    float s, c;
    sincosf(ph, &s, &c);
    __nv_bfloat16 sh = __float2bfloat16(s);
    __nv_bfloat16 ch = __float2bfloat16(c);
    float sr = s - __bfloat162float(sh);
    float cr = c - __bfloat162float(ch);
    __nv_bfloat162 hp(sh, ch);
    __nv_bfloat162 lp(__float2bfloat16(sr), __float2bfloat16(cr));
    int rl = e >> 9, col = e & 511;
    uint32_t off = (uint32_t)((col >> 5) * 2048)
                 + SWZ128((uint32_t)(rl * 128 + ((4 * col) & 127)));
    *(uint32_t*)(dynsm + BAS_HI + off) = *(uint32_t*)&hp;
    *(uint32_t*)(dynsm + BAS_LO + off) = *(uint32_t*)&lp;
  }
}

// ---------------- row-local bf16 mma GEMM: g_K[dst] rows = basis * C^T -------
// 48 chunks of K=64: seg0 Ah*Bh, seg1 Ah*Bl, seg2 Al*Bh. A in smem, B cp.async.
__device__ __forceinline__ void mma_bf16(float* c, uint32_t a0, uint32_t a1,
                                         uint32_t a2, uint32_t a3,
                                         uint32_t b0, uint32_t b1) {
  asm volatile("mma.sync.aligned.m16n8k16.row.col.f32.bf16.bf16.f32 "
               "{%0,%1,%2,%3}, {%4,%5,%6,%7}, {%8,%9}, {%0,%1,%2,%3};"
               : "+f"(c[0]), "+f"(c[1]), "+f"(c[2]), "+f"(c[3])
               : "r"(a0), "r"(a1), "r"(a2), "r"(a3), "r"(b0), "r"(b1));
}

__device__ void gemm_feval(int dst, int id, char* dynsm) {
  int tid = threadIdx.x, wid = tid >> 5, lane = tid & 31;
  int n0 = wid * 32;                 // warp owns 32 output cols
  int r0 = id * ROWS_PER;
  float* D = g_K[dst];
  uint32_t Ssm = smem_u32(dynsm);
  int g = lane >> 3, r = lane & 7;
  int a_m = ((g & 1) ? 8 : 0) + r;
  int a_k = (g >> 1) * 8;
  int b_n = ((g >> 1) ? 8 : 0) + r;
  int b_k = (g & 1) * 8;

  float acc[4][4] = {};

  auto issueB = [&](int ck) {
    int seg = ck >> 4, kc = ck & 15;
    const __nv_bfloat16* Bg = (seg == 1) ? g_Clo : g_Chi;
    uint32_t dstb = Ssm + BBUF0 + (uint32_t)((ck & 1) * BCHUNK);
    const __nv_bfloat16* src = Bg + kc * 64;
    #pragma unroll
    for (int i2 = 0; i2 < 8; i2++) {
      int q = tid + i2 * 512;
      int n = q >> 3, ch = q & 7;
      CP_ASYNC16(dstb + SWZ128((uint32_t)(n * 128 + ch * 16)),
                 src + (size_t)n * KFLAT + ch * 8);
    }
  };

  issueB(0); CP_COMMIT();
  for (int ck = 0; ck < 48; ck++) {
    if (ck < 47) issueB(ck + 1);
    CP_COMMIT();
    CP_WAIT1();
    __syncthreads();
    int seg = ck >> 4, kc = ck & 15;
    uint32_t Ab = Ssm + (seg == 2 ? BAS_LO : BAS_HI) + kc * 2048;
    uint32_t Bb = Ssm + BBUF0 + (ck & 1) * BCHUNK;
    #pragma unroll
    for (int kf = 0; kf < 4; kf++) {
      uint32_t a0, a1, a2, a3;
      uint32_t addrA = Ab + SWZ128((uint32_t)(a_m * 128 + (kf * 16 + a_k) * 2));
      asm volatile("ldmatrix.sync.aligned.m8n8.x4.shared.b16 {%0,%1,%2,%3}, [%4];"
                   : "=r"(a0), "=r"(a1), "=r"(a2), "=r"(a3) : "r"(addrA));
      #pragma unroll
      for (int ng = 0; ng < 2; ng++) {
        uint32_t b0, b1, b2, b3;
        uint32_t addrB = Bb + SWZ128((uint32_t)((n0 + ng * 16 + b_n) * 128 + (kf * 16 + b_k) * 2));
        asm volatile("ldmatrix.sync.aligned.m8n8.x4.shared.b16 {%0,%1,%2,%3}, [%4];"
                     : "=r"(b0), "=r"(b1), "=r"(b2), "=r"(b3) : "r"(addrB));
        mma_bf16(acc[ng * 2],     a0, a1, a2, a3, b0, b1);
        mma_bf16(acc[ng * 2 + 1], a0, a1, a2, a3, b2, b3);
      }
    }
    __syncthreads();
  }
  CP_WAIT0();

  // epilogue: row-local global writes
  int mr = r0 + (lane >> 2);
  int nc = (lane & 3) * 2;
  #pragma unroll
  for (int nt = 0; nt < 4; nt++) {
    int nb = n0 + nt * 8 + nc;
    float2 lo = {acc[nt][0], acc[nt][1]};
    float2 hi = {acc[nt][2], acc[nt][3]};
    *(float2*)&D[(size_t)mr * DIM + nb] = lo;
    *(float2*)&D[(size_t)(mr + 8) * DIM + nb] = hi;
  }
  __syncthreads();
}

// ---------------- block reduce (512 threads) ----------------
__device__ __forceinline__ float blockReduce(float v, float* sh) {
  int tid = threadIdx.x;
  sh[tid] = v; __syncthreads();
  for (int s = 256; s > 0; s >>= 1) {
    if (tid < s) sh[tid] += sh[tid + s];
    __syncthreads();
  }
  float r = sh[0];
  __syncthreads();
  return r;
}

__device__ __forceinline__ float gridSum(int slot) {
  float S = 0.f;
  for (int b = 0; b < NB; b++) S += __ldcg(&g_red[slot * NB + b]);
  return S;
}

// ---------------- persistent ODE kernel (row-local) ----------------
__global__ __launch_bounds__(NTH, 1) void k_ode() {
  extern __shared__ char dynsm[];
  __shared__ float sred[NTH];
  __shared__ int   s_epoch;
  int tid = threadIdx.x, id = blockIdx.x;
  if (tid == 0) s_epoch = 0;
  __syncthreads();
  int ebase = id * ELEMS_PER + tid;

  // ---- f0 = f(0, A0) ----
  stage_dev(0, 0, 0, 0.f, 0.f, id, dynsm);
  __syncthreads();
  gemm_feval(0, id, dynsm);

  // ---- d0, d1 partials ----
  {
    float s0 = 0.f, s1 = 0.f;
    #pragma unroll 4
    for (int it = 0; it < NPT_E; it++) {
      int i = ebase + it * NTH;
      float y = g_A[i], f = g_K[0][i];
      float sc = 1e-6f + 1e-3f * fabsf(y);
      float a = y / sc, b = f / sc;
      s0 += a * a; s1 += b * b;
    }
    float S0 = blockReduce(s0, sred);
    float S1 = blockReduce(s1, sred);
    if (tid == 0) { g_red[0 * NB + id] = S0; g_red[1 * NB + id] = S1; }
  }
  gridbar(&s_epoch);
  float d0 = sqrtf(gridSum(0) / (float)N_ELEM);
  float d1 = sqrtf(gridSum(1) / (float)N_ELEM);
  float h0 = (d0 < 1e-5f || d1 < 1e-5f) ? 1e-6f : 0.01f * d0 / d1;

  // ---- f1 = f(h0, y0 + h0*f0) -> g_K[1] ----
  stage_dev(1, 1, 0, h0, 0.f, id, dynsm);
  __syncthreads();
  gemm_feval(1, id, dynsm);
  {
    float s = 0.f;
    #pragma unroll 4
    for (int it = 0; it < NPT_E; it++) {
      int i = ebase + it * NTH;
      float y = g_A[i];
      float sc = 1e-6f + 1e-3f * fabsf(y);
      float d = (g_K[1][i] - g_K[0][i]) / sc;
      s += d * d;
    }
    float S = blockReduce(s, sred);
    if (tid == 0) g_red[2 * NB + id] = S;
  }
  gridbar(&s_epoch);
  float d2 = sqrtf(gridSum(2) / (float)N_ELEM) / h0;
  float dmax = fmaxf(d1, d2);
  float h1 = (dmax <= 1e-15f) ? fmaxf(1e-6f, h0 * 1e-3f)
                              : powf(0.01f / dmax, 0.2f);
  float h = fminf(fminf(100.f * h0, h1), 1.0f);
  float t = 0.f;

  // ---- adaptive loop: all phases CTA-local except 1 barrier/step ----
  for (int step = 0; step < 20; step++) {
    float hs = fminf(h, 1.0f - t);

    stage_dev(2, 1, 0, hs, t, id, dynsm); __syncthreads(); gemm_feval(1, id, dynsm);
    stage_dev(3, 2, 0, hs, t, id, dynsm); __syncthreads(); gemm_feval(2, id, dynsm);
    stage_dev(4, 3, 0, hs, t, id, dynsm); __syncthreads(); gemm_feval(3, id, dynsm);
    stage_dev(5, 4, 0, hs, t, id, dynsm); __syncthreads(); gemm_feval(4, id, dynsm);
    stage_dev(6, 5, 0, hs, t, id, dynsm); __syncthreads(); gemm_feval(5, id, dynsm);
    stage_dev(7, 6, 1, hs, t, id, dynsm); __syncthreads(); gemm_feval(6, id, dynsm);

    int slot = 3 + (step & 1);
    {
      float s = 0.f;
      #pragma unroll 2
      for (int it = 0; it < NPT_E; it++) {
        int i = ebase + it * NTH;
        float e = 0.f;
        #pragma unroll
        for (int j = 0; j < 6; j++)
          e += ERR_C[j] * g_K[ERR_IDX[j]][i];
        e *= hs;
        float y = g_A[i], yn = g_ynew[i];
        float sc = 1e-6f + 1e-3f * fmaxf(fabsf(y), fabsf(yn));
        float d = e / sc;
        s += d * d;
      }
      float S = blockReduce(s, sred);
      if (tid == 0) g_red[slot * NB + id] = S;
    }
    gridbar(&s_epoch);
    float en = sqrtf(gridSum(slot) / (float)N_ELEM);

    // replicated scalar control (identical in all threads/CTAs)
    int accept = en < 1.0f;
    float safe = fmaxf(en, 1e-10f);
    float p = 0.9f * powf(safe, -0.2f);
    float fac = accept ? fminf(10.f, p) : fmaxf(0.2f, p);
    if (accept) t = t + hs;
    h = hs * fac;

    if (accept) {
      #pragma unroll 4
      for (int it = 0; it < NPT_E; it++) {
        int i = ebase + it * NTH;
        g_A[i] = g_ynew[i];
        g_K[0][i] = g_K[6][i];   // FSAL
      }
    }
    if (t >= 1.0f - 1e-7f) break;
  }
}

// ---------------- barrier/state init ----------------
__global__ void k_init() { g_bar_cnt = 0; g_bar_epoch = 0; }

// ---------------- C hi/lo split ----------------
__global__ __launch_bounds__(256) void k_prep_C(const float* __restrict__ C) {
  int base = blockIdx.x * 1024 + threadIdx.x;
  #pragma unroll
  for (int r = 0; r < 4; r++) {
    int i = base + r * 256;
    float v = C[i];
    __nv_bfloat16 h = __float2bfloat16(v);
    g_Chi[i] = h;
    g_Clo[i] = __float2bfloat16(v - __bfloat162float(h));
  }
}

// ---------------- GEMM NN (SIMT fp32, 64x32 tiles, grid 16x8=128 blocks) ----
__global__ __launch_bounds__(256) void k_gemm_nn(const float* __restrict__ Aext,
                                                const float* __restrict__ Bm,
                                                float* outExt, int mode) {
  const float* A = mode ? g_A : Aext;
  float* D = mode ? outExt : g_A;
  const int K = DIM;
  __shared__ float As[16][64];
  __shared__ float Bs[16][32];
  int tid = threadIdx.x;
  int tx = tid & 15, ty = tid >> 4;
  int row0 = blockIdx.y * 64, col0 = blockIdx.x * 32;
  int lr = tid >> 2;
  int lc = (tid & 3) * 4;
  int br = tid >> 4;
  int bc = (tid & 15) * 2;
  float acc[4][2] = {};
  for (int k0 = 0; k0 < K; k0 += 16) {
    float4 av = *(const float4*)&A[(row0 + lr) * K + k0 + lc];
    As[lc+0][lr]=av.x; As[lc+1][lr]=av.y; As[lc+2][lr]=av.z; As[lc+3][lr]=av.w;
    float2 bv = *(const float2*)&Bm[(k0 + br) * DIM + col0 + bc];
    *(float2*)&Bs[br][bc] = bv;
    __syncthreads();
    #pragma unroll
    for (int kk = 0; kk < 16; kk++) {
      float4 a = *(const float4*)&As[kk][ty*4];
      float2 b = *(const float2*)&Bs[kk][tx*2];
      float ar[4] = {a.x,a.y,a.z,a.w};
      #pragma unroll
      for (int i = 0; i < 4; i++) {
        acc[i][0] += ar[i] * b.x;
        acc[i][1] += ar[i] * b.y;
      }
    }
    __syncthreads();
  }
  #pragma unroll
  for (int i = 0; i < 4; i++) {
    float2 o = {acc[i][0], acc[i][1]};
    *(float2*)&D[(row0 + ty*4 + i) * DIM + col0 + tx*2] = o;
  }
}

// ---------------- host launcher ----------------
extern "C" void kernel_launch(void* const* d_in, const int* in_sizes, int n_in,
                              void* d_out, int out_size) {
  const float* x = (const float*)d_in[0];
  const float* P = (const float*)d_in[1];
  const float* C = (const float*)d_in[2];
  const float* F = (const float*)d_in[3];
  float* out = (float*)d_out;

  static int smem_set = 0;
  if (!smem_set) {
    cudaFuncSetAttribute(k_ode, cudaFuncAttributeMaxDynamicSharedMemorySize, SMEM_DYN);
    smem_set = 1;
  }

  dim3 gNN(16, 8);

  k_init<<<1, 1>>>();
  k_prep_C<<<512, 256>>>(C);
  k_gemm_nn<<<gNN, 256>>>(x, P, nullptr, 0);     // A0 = x @ P
  k_ode<<<NB, NTH, SMEM_DYN>>>();                // entire RK45 integration
  k_gemm_nn<<<gNN, 256>>>(nullptr, F, out, 1);   // y_hat = A_f @ F
}

// round 13
// speedup vs baseline: 1.6365x; 1.6365x over previous
#include <cuda_runtime.h>
#include <cuda_bf16.h>
#include <math.h>
#include <stdint.h>

#define DIM   512
#define N_ELEM (DIM*DIM)       // 262144
#define KFLAT 1024             // DT*2
#define NB    128              // persistent CTAs (1/SM, all co-resident)
#define NTH   256
#define NPT   8                // elements/thread for elementwise phases

// dynamic smem layout (bytes)
#define BAS_HI 0               // A basis hi: 8 chunks x 8KB (64 rows x 128B, SW128)
#define BAS_LO 65536           // A basis lo: 64KB
#define BSTR   131072          // B double buffer: 2 x 8KB
#define SMEM_DYN (131072 + 2*8192)   // 147456

// ---------------- device state ----------------
__device__ float g_Y[2][N_ELEM];       // y double buffer
__device__ float g_K[7][2][N_ELEM];    // k arrays, split-K partials
__device__ __align__(16) __nv_bfloat16 g_Chi[DIM*KFLAT]; // C hi (row=out col, K contiguous)
__device__ __align__(16) __nv_bfloat16 g_Clo[DIM*KFLAT]; // C lo
__device__ float g_red[5*NB];
__device__ int   g_bar_cnt;
__device__ int   g_bar_epoch;
__device__ int   g_yfin;               // final y-buffer parity

// Dormand-Prince tables
__constant__ float STG_C[8][6] = {
  {0.f,0.f,0.f,0.f,0.f,0.f},
  {1.f,0.f,0.f,0.f,0.f,0.f},
  {0.2f,0.f,0.f,0.f,0.f,0.f},
  {3.f/40.f, 9.f/40.f, 0.f,0.f,0.f,0.f},
  {44.f/45.f, -56.f/15.f, 32.f/9.f, 0.f,0.f,0.f},
  {19372.f/6561.f, -25360.f/2187.f, 64448.f/6561.f, -212.f/729.f,0.f,0.f},
  {9017.f/3168.f, -355.f/33.f, 46732.f/5247.f, 49.f/176.f, -5103.f/18656.f, 0.f},
  {35.f/384.f, 0.f, 500.f/1113.f, 125.f/192.f, -2187.f/6784.f, 11.f/84.f},
};
__constant__ float STG_T[8] = {0.f, 1.f, 0.2f, 0.3f, 0.8f, 8.f/9.f, 1.f, 1.f};
__constant__ float ERR_C[6] = { 71.f/57600.f, -71.f/16695.f, 71.f/1920.f,
                                -17253.f/339200.f, 22.f/525.f, -1.f/40.f };

#define SWZ128(o) ((o) ^ (((o) >> 3) & 0x70))

__device__ __forceinline__ uint32_t smem_u32(const void* p) {
  uint32_t a;
  asm("{ .reg .u64 t; cvta.to.shared.u64 t, %1; cvt.u32.u64 %0, t; }" : "=r"(a) : "l"(p));
  return a;
}

// ---------------- grid barrier ----------------
__device__ __forceinline__ void gridbar(int* s_epoch) {
  __syncthreads();
  if (threadIdx.x == 0) {
    int e = ++(*s_epoch);
    __threadfence();
    if (atomicAdd(&g_bar_cnt, 1) == NB - 1) {
      g_bar_cnt = 0;
      __threadfence();
      atomicExch(&g_bar_epoch, e);
    } else {
      while (*((volatile int*)&g_bar_epoch) < e) { }
    }
    __threadfence();
  }
  __syncthreads();
}

__device__ __forceinline__ void mma_bf16(float* c, uint32_t a0, uint32_t a1,
                                         uint32_t a2, uint32_t a3,
                                         uint32_t b0, uint32_t b1) {
  asm volatile("mma.sync.aligned.m16n8k16.row.col.f32.bf16.bf16.f32 "
               "{%0,%1,%2,%3}, {%4,%5,%6,%7}, {%8,%9}, {%0,%1,%2,%3};"
               : "+f"(c[0]), "+f"(c[1]), "+f"(c[2]), "+f"(c[3])
               : "r"(a0), "r"(a1), "r"(a2), "r"(a3), "r"(b0), "r"(b1));
}

// ---------------- fused stage + GEMM f-eval ----------------
// Computes yt + basis (bf16 hi/lo) for this CTA's A tile directly into smem,
// then D tile = basis * C^T with 24 K64 chunks (seg0 Ah*Bh, seg1 Ah*Bl, seg2 Al*Bh).
__device__ void gemm_feval(int sid, int nK, int i1, int dst, int writeY,
                           float hs, float t, int ycur,
                           int bx, int row0, int col0, int j0, int kbase, int bz,
                           char* dynsm) {
  int tid = threadIdx.x;
  float ts = t + STG_T[sid] * hs;
  int doY = writeY && (bx == 0);

  // ---- phase 1: yt + sincos + hi/lo split -> smem basis (16K elems, 64/thread)
  // thread tid owns j-col (j0 + tid); iterates rows row0..row0+63
  {
    uint32_t cb = (uint32_t)((tid >> 5) * 8192) + ((4 * tid) & 127);
    #pragma unroll 2
    for (int it = 0; it < 64; it++) {
      int addr = (row0 + it) * DIM + j0 + tid;
      float y = __ldcg(&g_Y[ycur][addr]);
      float yt = y;
      if (nK > 0) {
        float acc = 0.f;
        #pragma unroll
        for (int j = 0; j < 6; j++) {
          if (j < nK) {
            int kidx = (j == 0) ? i1 : j;
            acc += STG_C[sid][j] * (__ldcg(&g_K[kidx][0][addr]) + __ldcg(&g_K[kidx][1][addr]));
          }
        }
        yt = y + hs * acc;
      }
      if (doY) g_Y[ycur ^ 1][addr] = yt;
      float s, c;
      sincosf(yt + ts, &s, &c);    // TA=1, TB=1, TC=0
      __nv_bfloat16 sh = __float2bfloat16(s);
      __nv_bfloat16 ch = __float2bfloat16(c);
      float sr = s - __bfloat162float(sh);
      float cr = c - __bfloat162float(ch);
      __nv_bfloat162 hp(sh, ch);
      __nv_bfloat162 lp(__float2bfloat16(sr), __float2bfloat16(cr));
      uint32_t off = (cb & 0xFFFFE000u) + SWZ128((cb & 0x1FFFu) + (uint32_t)(it * 128));
      *(uint32_t*)(dynsm + BAS_HI + off) = *(uint32_t*)&hp;
      *(uint32_t*)(dynsm + BAS_LO + off) = *(uint32_t*)&lp;
    }
  }

  // ---- phase 2: mma over 24 chunks, B streamed (register-staged double buffer)
  int wid = tid >> 5, lane = tid & 31;
  int wr = wid >> 2, wc = wid & 3;             // 2x4 warps, warp tile 32x16
  int g = lane >> 3, r = lane & 7;
  int a_m = ((g & 1) ? 8 : 0) + r;
  int a_k = (g >> 1) * 8;
  int b_n = ((g >> 1) ? 8 : 0) + r;
  int b_k = (g & 1) * 8;
  uint32_t Ssm = smem_u32(dynsm);

  int lrow0 = tid >> 3, lch0 = tid & 7;
  int c1 = tid + 256;
  int lrow1 = c1 >> 3, lch1 = c1 & 7;
  uint32_t so0 = SWZ128((uint32_t)(lrow0 * 128 + lch0 * 16));
  uint32_t so1 = SWZ128((uint32_t)(lrow1 * 128 + lch1 * 16));

  float acc[2][2][4] = {};

  // prologue: B chunk 0 -> buffer 0 (combined with basis sync)
  {
    const __nv_bfloat16* B = g_Chi;
    *(uint4*)(dynsm + BSTR + so0) = *(const uint4*)&B[(size_t)(col0 + lrow0) * KFLAT + kbase + lch0 * 8];
    *(uint4*)(dynsm + BSTR + so1) = *(const uint4*)&B[(size_t)(col0 + lrow1) * KFLAT + kbase + lch1 * 8];
  }
  __syncthreads();

  int cur = 0;
  for (int tk = 0; tk < 24; tk++) {
    uint4 bv0, bv1;
    if (tk < 23) {
      const __nv_bfloat16* B = (((tk + 1) >> 3) == 1) ? g_Clo : g_Chi;
      int koff = kbase + ((tk + 1) & 7) * 64;
      bv0 = *(const uint4*)&B[(size_t)(col0 + lrow0) * KFLAT + koff + lch0 * 8];
      bv1 = *(const uint4*)&B[(size_t)(col0 + lrow1) * KFLAT + koff + lch1 * 8];
    }
    int seg = tk >> 3, kc = tk & 7;
    uint32_t Ab = Ssm + (seg == 2 ? BAS_LO : BAS_HI) + kc * 8192;
    uint32_t Bb = Ssm + BSTR + cur * 8192;
    #pragma unroll
    for (int s = 0; s < 4; s++) {
      uint32_t b0, b1, b2, b3;
      uint32_t addrB = Bb + SWZ128((uint32_t)((wc * 16 + b_n) * 128 + (s * 16 + b_k) * 2));
      asm volatile("ldmatrix.sync.aligned.m8n8.x4.shared.b16 {%0,%1,%2,%3}, [%4];"
                   : "=r"(b0), "=r"(b1), "=r"(b2), "=r"(b3) : "r"(addrB));
      #pragma unroll
      for (int mf = 0; mf < 2; mf++) {
        uint32_t a0, a1, a2, a3;
        uint32_t addrA = Ab + SWZ128((uint32_t)((wr * 32 + mf * 16 + a_m) * 128 + (s * 16 + a_k) * 2));
        asm volatile("ldmatrix.sync.aligned.m8n8.x4.shared.b16 {%0,%1,%2,%3}, [%4];"
                     : "=r"(a0), "=r"(a1), "=r"(a2), "=r"(a3) : "r"(addrA));
        mma_bf16(acc[mf][0], a0, a1, a2, a3, b0, b1);
        mma_bf16(acc[mf][1], a0, a1, a2, a3, b2, b3);
      }
    }
    if (tk < 23) {
      int nxt = cur ^ 1;
      *(uint4*)(dynsm + BSTR + nxt * 8192 + so0) = bv0;
      *(uint4*)(dynsm + BSTR + nxt * 8192 + so1) = bv1;
      __syncthreads();
      cur = nxt;
    }
  }

  // epilogue
  float* D = &g_K[dst][bz][0];
  int mrow = row0 + wr * 32 + (lane >> 2);
  int ncol = col0 + wc * 16 + (lane & 3) * 2;
  #pragma unroll
  for (int mf = 0; mf < 2; mf++) {
    #pragma unroll
    for (int nf = 0; nf < 2; nf++) {
      float2 lo = {acc[mf][nf][0], acc[mf][nf][1]};
      float2 hi = {acc[mf][nf][2], acc[mf][nf][3]};
      *(float2*)&D[(size_t)(mrow + mf * 16)     * DIM + ncol + nf * 8] = lo;
      *(float2*)&D[(size_t)(mrow + mf * 16 + 8) * DIM + ncol + nf * 8] = hi;
    }
  }
  __syncthreads();
}

// ---------------- block reduce (256 threads) ----------------
__device__ __forceinline__ float blockReduce(float v, float* sh) {
  int tid = threadIdx.x;
  sh[tid] = v; __syncthreads();
  for (int s = 128; s > 0; s >>= 1) {
    if (tid < s) sh[tid] += sh[tid + s];
    __syncthreads();
  }
  float r = sh[0];
  __syncthreads();
  return r;
}

__device__ __forceinline__ float gridSum(int slot) {
  float S = 0.f;
  for (int b = 0; b < NB; b++) S += __ldcg(&g_red[slot * NB + b]);
  return S;
}

// ---------------- persistent ODE kernel ----------------
__global__ __launch_bounds__(NTH, 1) void k_ode() {
  extern __shared__ char dynsm[];
  __shared__ float sred[NTH];
  __shared__ int   s_epoch;
  int tid = threadIdx.x, id = blockIdx.x;
  int bx = id & 7, by = (id >> 3) & 7, bz = id >> 6;
  int row0 = by * 64, col0 = bx * 64, kbase = bz * 512, j0 = bz * 256;
  if (tid == 0) s_epoch = 0;
  __syncthreads();
  int ebase = id * (NTH * NPT) + tid;

  int ycur = 0, i1 = 0, i7 = 6;

  // ---- f0 = f(0, y0) -> k[i1] ----
  gemm_feval(0, 0, i1, i1, 0, 0.f, 0.f, ycur, bx, row0, col0, j0, kbase, bz, dynsm);
  gridbar(&s_epoch);

  // ---- d0, d1 ----
  {
    float s0 = 0.f, s1 = 0.f;
    #pragma unroll
    for (int r = 0; r < NPT; r++) {
      int i = ebase + r * NTH;
      float y = __ldcg(&g_Y[ycur][i]);
      float f = __ldcg(&g_K[i1][0][i]) + __ldcg(&g_K[i1][1][i]);
      float sc = 1e-6f + 1e-3f * fabsf(y);
      float a = y / sc, b = f / sc;
      s0 += a * a; s1 += b * b;
    }
    float S0 = blockReduce(s0, sred);
    float S1 = blockReduce(s1, sred);
    if (tid == 0) { g_red[0 * NB + id] = S0; g_red[1 * NB + id] = S1; }
  }
  gridbar(&s_epoch);
  float d0 = sqrtf(gridSum(0) / (float)N_ELEM);
  float d1 = sqrtf(gridSum(1) / (float)N_ELEM);
  float h0 = (d0 < 1e-5f || d1 < 1e-5f) ? 1e-6f : 0.01f * d0 / d1;

  // ---- f1 = f(h0, y0 + h0*f0) -> k[1] ----
  gemm_feval(1, 1, i1, 1, 0, h0, 0.f, ycur, bx, row0, col0, j0, kbase, bz, dynsm);
  gridbar(&s_epoch);
  {
    float s = 0.f;
    #pragma unroll
    for (int r = 0; r < NPT; r++) {
      int i = ebase + r * NTH;
      float y = __ldcg(&g_Y[ycur][i]);
      float sc = 1e-6f + 1e-3f * fabsf(y);
      float f0 = __ldcg(&g_K[i1][0][i]) + __ldcg(&g_K[i1][1][i]);
      float f1 = __ldcg(&g_K[1][0][i])  + __ldcg(&g_K[1][1][i]);
      float d = (f1 - f0) / sc;
      s += d * d;
    }
    float S = blockReduce(s, sred);
    if (tid == 0) g_red[2 * NB + id] = S;
  }
  gridbar(&s_epoch);
  float d2 = sqrtf(gridSum(2) / (float)N_ELEM) / h0;
  float dmax = fmaxf(d1, d2);
  float h1 = (dmax <= 1e-15f) ? fmaxf(1e-6f, h0 * 1e-3f)
                              : powf(0.01f / dmax, 0.2f);
  float h = fminf(fminf(100.f * h0, h1), 1.0f);
  float t = 0.f;

  // ---- adaptive loop: 7 barriers per step ----
  for (int step = 0; step < 20; step++) {
    float hs = fminf(h, 1.0f - t);

    gemm_feval(2, 1, i1, 1, 0, hs, t, ycur, bx, row0, col0, j0, kbase, bz, dynsm); gridbar(&s_epoch);
    gemm_feval(3, 2, i1, 2, 0, hs, t, ycur, bx, row0, col0, j0, kbase, bz, dynsm); gridbar(&s_epoch);
    gemm_feval(4, 3, i1, 3, 0, hs, t, ycur, bx, row0, col0, j0, kbase, bz, dynsm); gridbar(&s_epoch);
    gemm_feval(5, 4, i1, 4, 0, hs, t, ycur, bx, row0, col0, j0, kbase, bz, dynsm); gridbar(&s_epoch);
    gemm_feval(6, 5, i1, 5, 0, hs, t, ycur, bx, row0, col0, j0, kbase, bz, dynsm); gridbar(&s_epoch);
    gemm_feval(7, 6, i1, i7, 1, hs, t, ycur, bx, row0, col0, j0, kbase, bz, dynsm); gridbar(&s_epoch);

    int slot = 3 + (step & 1);
    {
      float s = 0.f;
      #pragma unroll 2
      for (int r = 0; r < NPT; r++) {
        int i = ebase + r * NTH;
        float e = ERR_C[0] * (__ldcg(&g_K[i1][0][i]) + __ldcg(&g_K[i1][1][i]))
                + ERR_C[1] * (__ldcg(&g_K[2][0][i])  + __ldcg(&g_K[2][1][i]))
                + ERR_C[2] * (__ldcg(&g_K[3][0][i])  + __ldcg(&g_K[3][1][i]))
                + ERR_C[3] * (__ldcg(&g_K[4][0][i])  + __ldcg(&g_K[4][1][i]))
                + ERR_C[4] * (__ldcg(&g_K[5][0][i])  + __ldcg(&g_K[5][1][i]))
                + ERR_C[5] * (__ldcg(&g_K[i7][0][i]) + __ldcg(&g_K[i7][1][i]));
        e *= hs;
        float y  = __ldcg(&g_Y[ycur][i]);
        float yn = __ldcg(&g_Y[ycur ^ 1][i]);
        float sc = 1e-6f + 1e-3f * fmaxf(fabsf(y), fabsf(yn));
        float d = e / sc;
        s += d * d;
      }
      float S = blockReduce(s, sred);
      if (tid == 0) g_red[slot * NB + id] = S;
    }
    gridbar(&s_epoch);
    float en = sqrtf(gridSum(slot) / (float)N_ELEM);

    // replicated scalar control
    int accept = en < 1.0f;
    float safe = fmaxf(en, 1e-10f);
    float p = 0.9f * powf(safe, -0.2f);
    float fac = accept ? fminf(10.f, p) : fmaxf(0.2f, p);
    if (accept) {
      t = t + hs;
      int tmp = i1; i1 = i7; i7 = tmp;   // FSAL: k1 <- k7 via index swap
      ycur ^= 1;                          // y <- ynew via buffer swap
    }
    h = hs * fac;
    if (t >= 1.0f - 1e-7f) break;
  }

  if (id == 0 && tid == 0) g_yfin = ycur;
}

// ---------------- barrier/state init ----------------
__global__ void k_init() { g_bar_cnt = 0; g_bar_epoch = 0; g_yfin = 0; }

// ---------------- C hi/lo split ----------------
__global__ __launch_bounds__(256) void k_prep_C(const float* __restrict__ C) {
  int base = blockIdx.x * 1024 + threadIdx.x;
  #pragma unroll
  for (int r = 0; r < 4; r++) {
    int i = base + r * 256;
    float v = C[i];
    __nv_bfloat16 h = __float2bfloat16(v);
    g_Chi[i] = h;
    g_Clo[i] = __float2bfloat16(v - __bfloat162float(h));
  }
}

// ---------------- GEMM NN (SIMT fp32, 64x32 tiles, grid 16x8) ----------------
__global__ __launch_bounds__(256) void k_gemm_nn(const float* __restrict__ Aext,
                                                const float* __restrict__ Bm,
                                                float* outExt, int mode) {
  const float* A = mode ? g_Y[g_yfin] : Aext;
  float* D = mode ? outExt : g_Y[0];
  const int K = DIM;
  __shared__ float As[16][64];
  __shared__ float Bs[16][32];
  int tid = threadIdx.x;
  int tx = tid & 15, ty = tid >> 4;
  int row0 = blockIdx.y * 64, col0 = blockIdx.x * 32;
  int lr = tid >> 2;
  int lc = (tid & 3) * 4;
  int br = tid >> 4;
  int bc = (tid & 15) * 2;
  float acc[4][2] = {};
  for (int k0 = 0; k0 < K; k0 += 16) {
    float4 av = *(const float4*)&A[(row0 + lr) * K + k0 + lc];
    As[lc+0][lr]=av.x; As[lc+1][lr]=av.y; As[lc+2][lr]=av.z; As[lc+3][lr]=av.w;
    float2 bv = *(const float2*)&Bm[(k0 + br) * DIM + col0 + bc];
    *(float2*)&Bs[br][bc] = bv;
    __syncthreads();
    #pragma unroll
    for (int kk = 0; kk < 16; kk++) {
      float4 a = *(const float4*)&As[kk][ty*4];
      float2 b = *(const float2*)&Bs[kk][tx*2];
      float ar[4] = {a.x,a.y,a.z,a.w};
      #pragma unroll
      for (int i = 0; i < 4; i++) {
        acc[i][0] += ar[i] * b.x;
        acc[i][1] += ar[i] * b.y;
      }
    }
    __syncthreads();
  }
  #pragma unroll
  for (int i = 0; i < 4; i++) {
    float2 o = {acc[i][0], acc[i][1]};
    *(float2*)&D[(row0 + ty*4 + i) * DIM + col0 + tx*2] = o;
  }
}

// ---------------- host launcher ----------------
extern "C" void kernel_launch(void* const* d_in, const int* in_sizes, int n_in,
                              void* d_out, int out_size) {
  const float* x = (const float*)d_in[0];
  const float* P = (const float*)d_in[1];
  const float* C = (const float*)d_in[2];
  const float* F = (const float*)d_in[3];
  float* out = (float*)d_out;

  static int smem_set = 0;
  if (!smem_set) {
    cudaFuncSetAttribute(k_ode, cudaFuncAttributeMaxDynamicSharedMemorySize, SMEM_DYN);
    smem_set = 1;
  }

  dim3 gNN(16, 8);

  k_init<<<1, 1>>>();
  k_prep_C<<<512, 256>>>(C);
  k_gemm_nn<<<gNN, 256>>>(x, P, nullptr, 0);     // y0 = x @ P
  k_ode<<<NB, NTH, SMEM_DYN>>>();                // entire RK45 integration
  k_gemm_nn<<<gNN, 256>>>(nullptr, F, out, 1);   // y_hat = y_f @ F
}